// round 13
// baseline (speedup 1.0000x reference)
#include <cuda_runtime.h>
#include <math.h>

#define BN 32
#define TN 4096
#define UN 256
#define NJ 1024
#define CL 8

// ---------------- static device scratch (no runtime allocation) -------------
// padded by one step row so the t+1 prefetch at t = TN-1 stays in bounds
__device__ float g_Zx[(size_t)(TN + 1) * BN * NJ];   // [t*32+b][j] input projection
__device__ float g_Wp[512 * NJ];                     // packed W: rows 0..255 s-part, 256..511 x-part; col j=g*256+u

// ---------------- helpers ----------------------------------------------------
__device__ __forceinline__ unsigned smem_u32(const void* p) {
    unsigned a;
    asm("{ .reg .u64 t; cvta.to.shared.u64 t, %1; cvt.u32.u64 %0, t; }"
        : "=r"(a) : "l"(p));
    return a;
}
__device__ __forceinline__ unsigned long long pk2(float v) {
    unsigned long long r; unsigned u = __float_as_uint(v);
    asm("mov.b64 %0, {%1, %1};" : "=l"(r) : "r"(u));
    return r;
}
__device__ __forceinline__ unsigned long long pack2(float lo, float hi) {
    unsigned long long r;
    asm("mov.b64 %0, {%1, %2};" : "=l"(r)
        : "r"(__float_as_uint(lo)), "r"(__float_as_uint(hi)));
    return r;
}
__device__ __forceinline__ unsigned long long fma2(unsigned long long a,
                                                   unsigned long long b,
                                                   unsigned long long c) {
    unsigned long long d;
    asm("fma.rn.f32x2 %0, %1, %2, %3;" : "=l"(d) : "l"(a), "l"(b), "l"(c));
    return d;
}
__device__ __forceinline__ float2 upk2(unsigned long long v) {
    unsigned lo, hi;
    asm("mov.b64 {%0, %1}, %2;" : "=r"(lo), "=r"(hi) : "l"(v));
    return make_float2(__uint_as_float(lo), __uint_as_float(hi));
}
__device__ __forceinline__ unsigned mapa_u32(unsigned local, unsigned rank) {
    unsigned r;
    asm("mapa.shared::cluster.u32 %0, %1, %2;" : "=r"(r) : "r"(local), "r"(rank));
    return r;
}
__device__ __forceinline__ void mbar_init(unsigned addr, unsigned cnt) {
    asm volatile("mbarrier.init.shared.b64 [%0], %1;" :: "r"(addr), "r"(cnt) : "memory");
}
__device__ __forceinline__ void mbar_expect_tx(unsigned addr, unsigned bytes) {
    asm volatile("mbarrier.arrive.expect_tx.shared.b64 _, [%0], %1;"
                 :: "r"(addr), "r"(bytes) : "memory");
}
// TMA-style wait: CTA-scope acquire, tight poll, no suspend hint.
__device__ __forceinline__ void mbar_wait(unsigned addr, unsigned parity) {
    asm volatile(
        "{\n\t"
        ".reg .pred P;\n\t"
        "WL_%=:\n\t"
        "mbarrier.try_wait.parity.acquire.cta.shared::cta.b64 P, [%0], %1;\n\t"
        "@!P bra WL_%=;\n\t"
        "}"
        :: "r"(addr), "r"(parity) : "memory");
}
// 8-byte async store (duplicated ct) to a cluster CTA's SMEM, tx-accounted
__device__ __forceinline__ void st_async_v2(unsigned addr, float v, unsigned rbar) {
    asm volatile(
        "st.async.shared::cluster.mbarrier::complete_tx::bytes.v2.f32 "
        "[%0], {%1, %1}, [%2];"
        :: "r"(addr), "f"(v), "r"(rbar) : "memory");
}
// unified gate nonlinearity: A + B / (1 + exp(s*z))
__device__ __forceinline__ float gatefn(float a, float A, float B) {
    float e = __expf(a);
    float r = __fdividef(B, 1.0f + e);
    return A + r;
}
__device__ __forceinline__ float tanh_fast(float z) {
    float e = __expf(2.0f * z);
    return 1.0f - __fdividef(2.0f, 1.0f + e);
}

// ---------------- alignment rotator (so ncu -s 5 lands on k_rec) ------------
__global__ void k_nop() {}

// ---------------- kernel 0: pack weights ------------------------------------
__global__ __launch_bounds__(256) void k_init(const float* __restrict__ Wf,
                                              const float* __restrict__ Wi,
                                              const float* __restrict__ Wc,
                                              const float* __restrict__ Wo) {
    int idx = blockIdx.x * blockDim.x + threadIdx.x;
    if (idx < 512 * 1024) {
        int k = idx >> 10, j = idx & 1023;
        int g = j >> 8,    u = j & 255;
        const float* W = (g == 0) ? Wf : (g == 1) ? Wi : (g == 2) ? Wc : Wo;
        g_Wp[idx] = W[k * 256 + u];
    }
}

// ---------------- kernel 1: input projection GEMM ---------------------------
__global__ __launch_bounds__(256) void k_gemm(const float* __restrict__ x) {
    __shared__ __align__(16) float As[16][64];
    __shared__ __align__(16) float Bs[16][64];

    const int tid = threadIdx.x;
    const int n0  = blockIdx.x * 64;
    const int m0  = blockIdx.y * 64;
    const int tm  = tid >> 4, tn = tid & 15;
    const int ar  = tid >> 2, akq = tid & 3;
    const int bkr = tid >> 4, bnq = tid & 15;

    const int m_glob = m0 + ar;
    const int bb = m_glob & 31, tt = m_glob >> 5;
    const float* arow = x + ((size_t)bb * TN + tt) * 256;

    unsigned long long a00=0, a01=0, a10=0, a11=0, a20=0, a21=0, a30=0, a31=0;

    float4 av = *(const float4*)(arow + akq * 4);
    float4 bv = *(const float4*)(g_Wp + (size_t)(256 + bkr) * NJ + n0 + bnq * 4);

    for (int k0 = 0; k0 < 256; k0 += 16) {
        __syncthreads();
        As[akq * 4 + 0][ar] = av.x;
        As[akq * 4 + 1][ar] = av.y;
        As[akq * 4 + 2][ar] = av.z;
        As[akq * 4 + 3][ar] = av.w;
        *(float4*)&Bs[bkr][bnq * 4] = bv;
        __syncthreads();

        if (k0 + 16 < 256) {
            av = *(const float4*)(arow + k0 + 16 + akq * 4);
            bv = *(const float4*)(g_Wp + (size_t)(256 + k0 + 16 + bkr) * NJ + n0 + bnq * 4);
        }
        #pragma unroll
        for (int kk = 0; kk < 16; kk++) {
            float4 a = *(const float4*)&As[kk][tm * 4];
            ulonglong2 w = *(const ulonglong2*)&Bs[kk][tn * 4];
            unsigned long long p;
            p = pk2(a.x); a00 = fma2(p, w.x, a00); a01 = fma2(p, w.y, a01);
            p = pk2(a.y); a10 = fma2(p, w.x, a10); a11 = fma2(p, w.y, a11);
            p = pk2(a.z); a20 = fma2(p, w.x, a20); a21 = fma2(p, w.y, a21);
            p = pk2(a.w); a30 = fma2(p, w.x, a30); a31 = fma2(p, w.y, a31);
        }
    }
    float2 lo, hi;
    lo = upk2(a00); hi = upk2(a01);
    *(float4*)(g_Zx + (size_t)(m0 + tm*4 + 0) * NJ + n0 + tn*4) = make_float4(lo.x, lo.y, hi.x, hi.y);
    lo = upk2(a10); hi = upk2(a11);
    *(float4*)(g_Zx + (size_t)(m0 + tm*4 + 1) * NJ + n0 + tn*4) = make_float4(lo.x, lo.y, hi.x, hi.y);
    lo = upk2(a20); hi = upk2(a21);
    *(float4*)(g_Zx + (size_t)(m0 + tm*4 + 2) * NJ + n0 + tn*4) = make_float4(lo.x, lo.y, hi.x, hi.y);
    lo = upk2(a30); hi = upk2(a31);
    *(float4*)(g_Zx + (size_t)(m0 + tm*4 + 3) * NJ + n0 + tn*4) = make_float4(lo.x, lo.y, hi.x, hi.y);
}

// ---------------- kernel 2: persistent recurrence ----------------------------
// 16 clusters x 8 CTAs; cluster owns batches {2c,2c+1}; CTA rank r owns
// u-slice [r*32,r*32+32), weights in registers. Warp w owns k-slice
// [32w,32w+32) == u-slice of source w -> waits mbars[.][w].
// ISSUE DIET vs R11: state pre-duplicated in SMEM as [k][{s0,s0,s1,s1}] so one
// broadcast LDS.128 per k feeds fma2 directly (no pk2 movs); partials stored
// as STS.64 u64 pairs (no upk2); pushes send (ct,ct) as st.async.v2 (512B/src).
__global__ __launch_bounds__(256, 1) __cluster_dims__(CL, 1, 1)
void k_rec(float* __restrict__ out, const float* __restrict__ h0) {
    __shared__ __align__(16) float Ssm[2][256][4];     // [parity][k][{b0,b0,b1,b1}]
    __shared__ __align__(16) float Zsm[2][8][264];     // [parity][kg][b*128 + pos]
    __shared__ __align__(8)  unsigned long long mbars[2][8];  // [set = p&1][source]

    const int tid  = threadIdx.x;
    const int lane = tid & 31;
    const int wid  = tid >> 5;
    unsigned r;
    asm("mov.u32 %0, %%cluster_ctarank;" : "=r"(r));
    const int team = blockIdx.x >> 3;
    const int b0   = team * 2;
    const int u0   = (int)r * 32;

    const int jq = lane, kbeg = wid * 32;        // matmul: warp = k-slice
    const int jj = tid & 127, bb = tid >> 7;     // reduce/gate role: column jj
    const int gg = jj & 3,    uu = jj >> 2;
    const int jcol = gg * 256 + u0 + uu;
    // partial position of column jj inside a Zsm row half (STS.64 layout):
    // c = jq + 64m + 32s  ->  pos = 64m + 2*jq + s
    const int pos = ((jj >> 6) << 6) + ((jj & 31) << 1) + ((jj >> 5) & 1);
    const size_t c_off = (size_t)BN * TN * UN;

    if (tid < 16) mbar_init(smem_u32(&mbars[tid >> 3][tid & 7]), 1);

    // initial state for step 0 (duplicated layout)
    {
        float s0v = h0[(b0 + 0) * 256 + tid];
        float s1v = h0[(b0 + 1) * 256 + tid];
        Ssm[0][tid][0] = s0v; Ssm[0][tid][1] = s0v;
        Ssm[0][tid][2] = s1v; Ssm[0][tid][3] = s1v;
    }

    // gate-fn constants (f,i,g: sigmoid; o: tanh)
    const float gA = (gg == 3) ? 1.0f : 0.0f;
    const float gB = (gg == 3) ? -2.0f : 1.0f;
    const float gS = (gg == 3) ? 2.0f : -1.0f;

    // weights -> registers: w[k][m] packs cols (jq+64m, jq+64m+32), k in slice
    unsigned long long w[32][2];
    #pragma unroll
    for (int k = 0; k < 32; k++) {
        const float* row = g_Wp + (size_t)(kbeg + k) * NJ;
        #pragma unroll
        for (int m = 0; m < 2; m++) {
            int jA = jq + 64 * m, jB = jA + 32;
            int cA = (jA & 3) * 256 + u0 + (jA >> 2);
            int cB = (jB & 3) * 256 + u0 + (jB >> 2);
            w[k][m] = pack2(__ldg(row + cA), __ldg(row + cB));
        }
    }

    // remote addressing: one mapa base per rank; offsets are rank-invariant
    const unsigned SsmB = smem_u32(&Ssm[0][0][0]);
    unsigned m0v[8];
    #pragma unroll
    for (int rk = 0; rk < 8; rk++) m0v[rk] = mapa_u32(SsmB, (unsigned)rk);
    const unsigned barDelta = smem_u32(&mbars[0][0]) - SsmB + (unsigned)r * 8;
    // push target byte offset: Ssm[.][u0+uu][bb*2]
    const unsigned pushOffB = (unsigned)((u0 + uu) * 16 + bb * 8);

    const unsigned mywait0 = smem_u32(&mbars[0][wid]);
    const unsigned mywait1 = smem_u32(&mbars[1][wid]);

    // pre-arm both barrier sets: 1 arrive + 512B (64 thr x 8B per source)
    if (lane == 0) {
        mbar_expect_tx(mywait0, 512);
        mbar_expect_tx(mywait1, 512);
    }

    // hoisted Zsm row pointers for this warp's partial stores
    unsigned long long* zrow0 = (unsigned long long*)&Zsm[0][wid][0];
    unsigned long long* zrow1 = (unsigned long long*)&Zsm[1][wid][0];

    // per-step incremented pointers
    const float* zxp = g_Zx + (size_t)(b0 + bb) * NJ + jcol;     // += 32*NJ
    float* outH = out + (size_t)(b0 + bb) * TN * UN + (u0 + uu); // += UN

    __syncthreads();
    asm volatile("barrier.cluster.arrive.aligned;" ::: "memory");
    asm volatile("barrier.cluster.wait.aligned;" ::: "memory");

    float zx_cur = __ldcg(zxp);   // input projection, one step ahead

    for (int t = 0; t < TN; t++) {
        const int cur = t & 1;

        float zx_nxt = __ldcg(zxp + 32 * NJ);
        zxp += 32 * NJ;

        // warp-sliced wait on this warp's source slice (push #t-1), re-arm
        if (t > 0) {
            const int e = t - 1;
            const unsigned bar = (e & 1) ? mywait1 : mywait0;
            mbar_wait(bar, (unsigned)((e >> 1) & 1));
            if (lane == 0) mbar_expect_tx(bar, 512);
        }

        // recurrent matmul: 32 k, one broadcast LDS.128 per k -> fma2 operands
        unsigned long long a00=0, a01=0, a10=0, a11=0;
        const ulonglong2* Sp = (const ulonglong2*)&Ssm[cur][kbeg][0];
        #pragma unroll
        for (int k = 0; k < 32; k++) {
            ulonglong2 sv = Sp[k];          // sv.x=(s0,s0)  sv.y=(s1,s1)
            a00 = fma2(sv.x, w[k][0], a00); a01 = fma2(sv.x, w[k][1], a01);
            a10 = fma2(sv.y, w[k][0], a10); a11 = fma2(sv.y, w[k][1], a11);
        }
        // STS.64 partials: pos layout, lane-stride 8B (conflict-free)
        {
            unsigned long long* zr = cur ? zrow1 : zrow0;
            zr[      jq] = a00;   // b0, cols (jq, jq+32)      -> pos 2jq,2jq+1
            zr[ 32 + jq] = a01;   // b0, cols (jq+64, jq+96)   -> pos 64+2jq..
            zr[ 64 + jq] = a10;   // b1 half starts at float 128 = u64 64
            zr[ 96 + jq] = a11;
        }

        __syncthreads();   // the ONLY block sync per step

        // reduce 8 k-partials + input projection
        float z = zx_cur;
        #pragma unroll
        for (int g = 0; g < 8; g++) z += Zsm[cur][g][bb * 128 + pos];
        zx_cur = zx_nxt;

        // branch-free nonlinearity, gather 4 gates via shuffle
        float v = gatefn(gS * z, gA, gB);
        const int base = lane & ~3;
        float fv = __shfl_sync(0xFFFFFFFFu, v, base + 0);
        float iv = __shfl_sync(0xFFFFFFFFu, v, base + 1);
        float gv = __shfl_sync(0xFFFFFFFFu, v, base + 2);
        float ov = __shfl_sync(0xFFFFFFFFu, v, base + 3);

        if ((tid & 3) == 0) {
            float s_old = Ssm[cur][u0 + uu][bb * 2];
            float c  = iv * gv + fv * s_old;
            float ct = tanh_fast(c);
            float h  = ov * ct;
            // push (ct,ct) immediately: 8 async v2 stores, tx-accounted remotely
            if (t + 1 < TN) {
                const unsigned po = pushOffB + (unsigned)(((t + 1) & 1) * 4096);
                const unsigned bo = barDelta + (unsigned)((t & 1) * 64);
                #pragma unroll
                for (int rk = 0; rk < 8; rk++)
                    st_async_v2(m0v[rk] + po, ct, m0v[rk] + bo);
            }
            outH[0]     = h;
            outH[c_off] = ct;
        }
        outH += UN;
    }
}

// ---------------- launcher ---------------------------------------------------
extern "C" void kernel_launch(void* const* d_in, const int* in_sizes, int n_in,
                              void* d_out, int out_size) {
    const float* x  = (const float*)d_in[0];
    const float* h0 = (const float*)d_in[1];
    const float* Wf = (const float*)d_in[2];
    const float* Wi = (const float*)d_in[3];
    const float* Wc = (const float*)d_in[4];
    const float* Wo = (const float*)d_in[5];
    float* out = (float*)d_out;

    k_nop<<<1, 1>>>();
    k_init<<<2048, 256>>>(Wf, Wi, Wc, Wo);
    dim3 gg(NJ / 64, (TN * BN) / 64);   // (16, 2048)
    k_gemm<<<gg, 256>>>(x);
    k_rec<<<128, 256>>>(out, h0);
}

// round 14
// speedup vs baseline: 1.1837x; 1.1837x over previous
#include <cuda_runtime.h>
#include <math.h>

#define BN 32
#define TN 4096
#define UN 256
#define NJ 1024
#define CL 8

// ---------------- static device scratch (no runtime allocation) -------------
// padded by one step row so the t+1 prefetch at t = TN-1 stays in bounds
__device__ float g_Zx[(size_t)(TN + 1) * BN * NJ];   // [t*32+b][j] input projection
__device__ float g_Wp[512 * NJ];                     // packed W: rows 0..255 s-part, 256..511 x-part; col j=g*256+u

// ---------------- helpers ----------------------------------------------------
__device__ __forceinline__ unsigned smem_u32(const void* p) {
    unsigned a;
    asm("{ .reg .u64 t; cvta.to.shared.u64 t, %1; cvt.u32.u64 %0, t; }"
        : "=r"(a) : "l"(p));
    return a;
}
__device__ __forceinline__ unsigned long long pk2(float v) {
    unsigned long long r; unsigned u = __float_as_uint(v);
    asm("mov.b64 %0, {%1, %1};" : "=l"(r) : "r"(u));
    return r;
}
__device__ __forceinline__ unsigned long long pack2(float lo, float hi) {
    unsigned long long r;
    asm("mov.b64 %0, {%1, %2};" : "=l"(r)
        : "r"(__float_as_uint(lo)), "r"(__float_as_uint(hi)));
    return r;
}
__device__ __forceinline__ unsigned long long fma2(unsigned long long a,
                                                   unsigned long long b,
                                                   unsigned long long c) {
    unsigned long long d;
    asm("fma.rn.f32x2 %0, %1, %2, %3;" : "=l"(d) : "l"(a), "l"(b), "l"(c));
    return d;
}
__device__ __forceinline__ float2 upk2(unsigned long long v) {
    unsigned lo, hi;
    asm("mov.b64 {%0, %1}, %2;" : "=r"(lo), "=r"(hi) : "l"(v));
    return make_float2(__uint_as_float(lo), __uint_as_float(hi));
}
__device__ __forceinline__ unsigned mapa_u32(unsigned local, unsigned rank) {
    unsigned r;
    asm("mapa.shared::cluster.u32 %0, %1, %2;" : "=r"(r) : "r"(local), "r"(rank));
    return r;
}
__device__ __forceinline__ void mbar_init(unsigned addr, unsigned cnt) {
    asm volatile("mbarrier.init.shared.b64 [%0], %1;" :: "r"(addr), "r"(cnt) : "memory");
}
__device__ __forceinline__ void mbar_expect_tx(unsigned addr, unsigned bytes) {
    asm volatile("mbarrier.arrive.expect_tx.shared.b64 _, [%0], %1;"
                 :: "r"(addr), "r"(bytes) : "memory");
}
// TMA-style wait: CTA-scope acquire, tight poll, no suspend hint.
__device__ __forceinline__ void mbar_wait(unsigned addr, unsigned parity) {
    asm volatile(
        "{\n\t"
        ".reg .pred P;\n\t"
        "WL_%=:\n\t"
        "mbarrier.try_wait.parity.acquire.cta.shared::cta.b64 P, [%0], %1;\n\t"
        "@!P bra WL_%=;\n\t"
        "}"
        :: "r"(addr), "r"(parity) : "memory");
}
// scalar async store to a cluster CTA's SMEM, tx-accounted at remote mbarrier
__device__ __forceinline__ void st_async_f32(unsigned addr, float v, unsigned rbar) {
    asm volatile(
        "st.async.shared::cluster.mbarrier::complete_tx::bytes.f32 [%0], %1, [%2];"
        :: "r"(addr), "f"(v), "r"(rbar) : "memory");
}
// unified gate nonlinearity: A + B / (1 + exp(s*z))
__device__ __forceinline__ float gatefn(float a, float A, float B) {
    float e = __expf(a);
    float r = __fdividef(B, 1.0f + e);
    return A + r;
}
__device__ __forceinline__ float tanh_fast(float z) {
    float e = __expf(2.0f * z);
    return 1.0f - __fdividef(2.0f, 1.0f + e);
}

// ---------------- alignment rotator (so ncu -s 5 lands on k_rec) ------------
__global__ void k_nop() {}

// ---------------- kernel 0: pack weights ------------------------------------
__global__ __launch_bounds__(256) void k_init(const float* __restrict__ Wf,
                                              const float* __restrict__ Wi,
                                              const float* __restrict__ Wc,
                                              const float* __restrict__ Wo) {
    int idx = blockIdx.x * blockDim.x + threadIdx.x;
    if (idx < 512 * 1024) {
        int k = idx >> 10, j = idx & 1023;
        int g = j >> 8,    u = j & 255;
        const float* W = (g == 0) ? Wf : (g == 1) ? Wi : (g == 2) ? Wc : Wo;
        g_Wp[idx] = W[k * 256 + u];
    }
}

// ---------------- kernel 1: input projection GEMM ---------------------------
__global__ __launch_bounds__(256) void k_gemm(const float* __restrict__ x) {
    __shared__ __align__(16) float As[16][64];
    __shared__ __align__(16) float Bs[16][64];

    const int tid = threadIdx.x;
    const int n0  = blockIdx.x * 64;
    const int m0  = blockIdx.y * 64;
    const int tm  = tid >> 4, tn = tid & 15;
    const int ar  = tid >> 2, akq = tid & 3;
    const int bkr = tid >> 4, bnq = tid & 15;

    const int m_glob = m0 + ar;
    const int bb = m_glob & 31, tt = m_glob >> 5;
    const float* arow = x + ((size_t)bb * TN + tt) * 256;

    unsigned long long a00=0, a01=0, a10=0, a11=0, a20=0, a21=0, a30=0, a31=0;

    float4 av = *(const float4*)(arow + akq * 4);
    float4 bv = *(const float4*)(g_Wp + (size_t)(256 + bkr) * NJ + n0 + bnq * 4);

    for (int k0 = 0; k0 < 256; k0 += 16) {
        __syncthreads();
        As[akq * 4 + 0][ar] = av.x;
        As[akq * 4 + 1][ar] = av.y;
        As[akq * 4 + 2][ar] = av.z;
        As[akq * 4 + 3][ar] = av.w;
        *(float4*)&Bs[bkr][bnq * 4] = bv;
        __syncthreads();

        if (k0 + 16 < 256) {
            av = *(const float4*)(arow + k0 + 16 + akq * 4);
            bv = *(const float4*)(g_Wp + (size_t)(256 + k0 + 16 + bkr) * NJ + n0 + bnq * 4);
        }
        #pragma unroll
        for (int kk = 0; kk < 16; kk++) {
            float4 a = *(const float4*)&As[kk][tm * 4];
            ulonglong2 w = *(const ulonglong2*)&Bs[kk][tn * 4];
            unsigned long long p;
            p = pk2(a.x); a00 = fma2(p, w.x, a00); a01 = fma2(p, w.y, a01);
            p = pk2(a.y); a10 = fma2(p, w.x, a10); a11 = fma2(p, w.y, a11);
            p = pk2(a.z); a20 = fma2(p, w.x, a20); a21 = fma2(p, w.y, a21);
            p = pk2(a.w); a30 = fma2(p, w.x, a30); a31 = fma2(p, w.y, a31);
        }
    }
    float2 lo, hi;
    lo = upk2(a00); hi = upk2(a01);
    *(float4*)(g_Zx + (size_t)(m0 + tm*4 + 0) * NJ + n0 + tn*4) = make_float4(lo.x, lo.y, hi.x, hi.y);
    lo = upk2(a10); hi = upk2(a11);
    *(float4*)(g_Zx + (size_t)(m0 + tm*4 + 1) * NJ + n0 + tn*4) = make_float4(lo.x, lo.y, hi.x, hi.y);
    lo = upk2(a20); hi = upk2(a21);
    *(float4*)(g_Zx + (size_t)(m0 + tm*4 + 2) * NJ + n0 + tn*4) = make_float4(lo.x, lo.y, hi.x, hi.y);
    lo = upk2(a30); hi = upk2(a31);
    *(float4*)(g_Zx + (size_t)(m0 + tm*4 + 3) * NJ + n0 + tn*4) = make_float4(lo.x, lo.y, hi.x, hi.y);
}

// ---------------- kernel 2: persistent recurrence ----------------------------
// R11 protocol (best: 8209us) with 512 threads for latency hiding (occ 25%).
// 16 clusters x 8 CTAs; cluster owns batches {2c,2c+1}; CTA rank r owns
// u-slice [r*32,r*32+32). 16 warps: warp w owns k-slice [16w,16w+16) and waits
// source w>>1's barrier; even warp of each pair re-arms it. Gates/push/output
// on tid<256 exactly as R11 (push = 8 scalar st.async per gate thread).
__global__ __launch_bounds__(512, 1) __cluster_dims__(CL, 1, 1)
void k_rec(float* __restrict__ out, const float* __restrict__ h0) {
    __shared__ __align__(16) float Ssm[2][512];        // [parity][k*2 + b]
    __shared__ __align__(16) float Zsm[2][16][264];    // [parity][warp][b*128 + jj]
    __shared__ __align__(8)  unsigned long long mbars[2][8];  // [set = p&1][source]

    const int tid  = threadIdx.x;
    const int lane = tid & 31;
    const int wid  = tid >> 5;
    unsigned r;
    asm("mov.u32 %0, %%cluster_ctarank;" : "=r"(r));
    const int team = blockIdx.x >> 3;
    const int b0   = team * 2;
    const int u0   = (int)r * 32;

    const int jq = lane, kbeg = wid * 16;        // matmul: warp = 16-wide k-slice
    const int jj = tid & 127, bb = (tid >> 7) & 1;  // reduce/gate role (tid<256)
    const int gg = jj & 3,    uu = jj >> 2;
    const int jcol = gg * 256 + u0 + uu;
    const size_t c_off = (size_t)BN * TN * UN;

    if (tid < 16) mbar_init(smem_u32(&mbars[tid >> 3][tid & 7]), 1);

    // initial state for step 0
    if (tid < 256) {
        Ssm[0][tid * 2 + 0] = h0[(b0 + 0) * 256 + tid];
        Ssm[0][tid * 2 + 1] = h0[(b0 + 1) * 256 + tid];
    }

    // gate-fn constants (f,i,g: sigmoid; o: tanh)
    const float gA = (gg == 3) ? 1.0f : 0.0f;
    const float gB = (gg == 3) ? -2.0f : 1.0f;
    const float gS = (gg == 3) ? 2.0f : -1.0f;

    // weights -> registers: w[k][m] packs cols (jq+64m, jq+64m+32), k in slice
    unsigned long long w[16][2];
    #pragma unroll
    for (int k = 0; k < 16; k++) {
        const float* row = g_Wp + (size_t)(kbeg + k) * NJ;
        #pragma unroll
        for (int m = 0; m < 2; m++) {
            int jA = jq + 64 * m, jB = jA + 32;
            int cA = (jA & 3) * 256 + u0 + (jA >> 2);
            int cB = (jB & 3) * 256 + u0 + (jB >> 2);
            w[k][m] = pack2(__ldg(row + cA), __ldg(row + cB));
        }
    }

    // remote addressing: one mapa base per rank; offsets are rank-invariant
    const unsigned SsmB = smem_u32(&Ssm[0][0]);
    unsigned m0v[8];
    #pragma unroll
    for (int rk = 0; rk < 8; rk++) m0v[rk] = mapa_u32(SsmB, (unsigned)rk);
    const unsigned barDelta = smem_u32(&mbars[0][0]) - SsmB + (unsigned)r * 8;
    const unsigned pushOffB = (unsigned)(((u0 + uu) * 2 + bb) * 4);

    const unsigned mywait0 = smem_u32(&mbars[0][wid >> 1]);
    const unsigned mywait1 = smem_u32(&mbars[1][wid >> 1]);
    const bool rearm = (lane == 0) && ((wid & 1) == 0);

    // pre-arm both barrier sets (before cluster barrier -> precedes any push)
    if (rearm) {
        mbar_expect_tx(mywait0, 256);
        mbar_expect_tx(mywait1, 256);
    }

    // per-step incremented pointers
    const float* zxp = g_Zx + (size_t)(b0 + bb) * NJ + jcol;     // += 32*NJ
    float* outH = out + (size_t)(b0 + bb) * TN * UN + (u0 + uu); // += UN

    __syncthreads();
    asm volatile("barrier.cluster.arrive.aligned;" ::: "memory");
    asm volatile("barrier.cluster.wait.aligned;" ::: "memory");

    float zx_cur = (tid < 256) ? __ldcg(zxp) : 0.0f;

    for (int t = 0; t < TN; t++) {
        const int cur = t & 1;

        float zx_nxt = (tid < 256) ? __ldcg(zxp + 32 * NJ) : 0.0f;
        zxp += 32 * NJ;

        // warp-sliced wait on this warp's source slice (push #t-1); even warp
        // of the pair re-arms (before our push #t, which gates push #t+1)
        if (t > 0) {
            const int e = t - 1;
            const unsigned bar = (e & 1) ? mywait1 : mywait0;
            mbar_wait(bar, (unsigned)((e >> 1) & 1));
            if (rearm) mbar_expect_tx(bar, 256);
        }

        // recurrent matmul: 16 k x 2 u64 x 2 batches, weights in registers
        unsigned long long a00=0, a01=0, a10=0, a11=0;
        const float2* Sp = (const float2*)&Ssm[cur][kbeg * 2];
        #pragma unroll
        for (int k = 0; k < 16; k++) {
            float2 s = Sp[k];
            unsigned long long p0 = pk2(s.x), p1 = pk2(s.y);
            a00 = fma2(p0, w[k][0], a00); a01 = fma2(p0, w[k][1], a01);
            a10 = fma2(p1, w[k][0], a10); a11 = fma2(p1, w[k][1], a11);
        }
        // conflict-free partial stores (lane-consecutive STS.32), R11 layout
        {
            float* zr = &Zsm[cur][wid][0];
            float2 v;
            v = upk2(a00); zr[      jq]      = v.x; zr[      jq + 32] = v.y;
            v = upk2(a01); zr[      jq + 64] = v.x; zr[      jq + 96] = v.y;
            v = upk2(a10); zr[128 + jq]      = v.x; zr[128 + jq + 32] = v.y;
            v = upk2(a11); zr[128 + jq + 64] = v.x; zr[128 + jq + 96] = v.y;
        }

        __syncthreads();   // the ONLY block sync per step

        if (tid < 256) {
            // reduce 16 k-partials + input projection
            float z = zx_cur;
            #pragma unroll
            for (int g = 0; g < 16; g++) z += Zsm[cur][g][bb * 128 + jj];
            zx_cur = zx_nxt;

            // branch-free nonlinearity, gather 4 gates via shuffle
            float v = gatefn(gS * z, gA, gB);
            const int base = lane & ~3;
            float fv = __shfl_sync(0xFFFFFFFFu, v, base + 0);
            float iv = __shfl_sync(0xFFFFFFFFu, v, base + 1);
            float gv = __shfl_sync(0xFFFFFFFFu, v, base + 2);
            float ov = __shfl_sync(0xFFFFFFFFu, v, base + 3);

            if ((tid & 3) == 0) {
                float s_old = Ssm[cur][(u0 + uu) * 2 + bb];
                float c  = iv * gv + fv * s_old;
                float ct = tanh_fast(c);
                float h  = ov * ct;
                // push ct immediately: 8 async scalar stores, tx-accounted
                if (t + 1 < TN) {
                    const unsigned po = pushOffB + (unsigned)(((t + 1) & 1) * 2048);
                    const unsigned bo = barDelta + (unsigned)((t & 1) * 64);
                    #pragma unroll
                    for (int rk = 0; rk < 8; rk++)
                        st_async_f32(m0v[rk] + po, ct, m0v[rk] + bo);
                }
                outH[0]     = h;
                outH[c_off] = ct;
            }
            outH += UN;
        }
    }
}

// ---------------- launcher ---------------------------------------------------
extern "C" void kernel_launch(void* const* d_in, const int* in_sizes, int n_in,
                              void* d_out, int out_size) {
    const float* x  = (const float*)d_in[0];
    const float* h0 = (const float*)d_in[1];
    const float* Wf = (const float*)d_in[2];
    const float* Wi = (const float*)d_in[3];
    const float* Wc = (const float*)d_in[4];
    const float* Wo = (const float*)d_in[5];
    float* out = (float*)d_out;

    k_nop<<<1, 1>>>();
    k_init<<<2048, 256>>>(Wf, Wi, Wc, Wo);
    dim3 gg(NJ / 64, (TN * BN) / 64);   // (16, 2048)
    k_gemm<<<gg, 256>>>(x);
    k_rec<<<128, 512>>>(out, h0);
}